// round 2
// baseline (speedup 1.0000x reference)
#include <cuda_runtime.h>

#define Bb 2
#define Nn 16384
#define Mm 8192
#define Kk 2048
#define Rr 128

// ---------------- scratch (__device__ globals; no allocation allowed) ----------------
__device__ float g_px[Bb*Nn], g_py[Bb*Nn], g_pz[Bb*Nn];
__device__ float g_qx[Bb*Mm], g_qy[Bb*Mm], g_qz[Bb*Mm];
__device__ float g_fraw[Bb*Nn*32];
__device__ float g_fc3[Bb*Mm*64];
__device__ int   g_flag[Bb*Nn];
__device__ float g_cx[Bb*Nn], g_cy[Bb*Nn], g_cz[Bb*Nn];
__device__ int   g_vcount[Bb];
__device__ float g_kpx[Bb*Kk], g_kpy[Bb*Kk], g_kpz[Bb*Kk];
__device__ float g_feats[Bb*Kk*352];

// ---------------- prep: point SoA + raw point features relu(pf @ W_raw + b) ----------
__global__ void prep_raw_kernel(const float* __restrict__ points,
                                const float* __restrict__ W,
                                const float* __restrict__ bias) {
    int gid = blockIdx.x * 256 + threadIdx.x;      // Bb*Nn*32 threads
    int p = gid >> 5, c = gid & 31;
    const float* pp = points + (size_t)p * 5;
    float v = fmaxf(pp[3] * W[c] + pp[4] * W[32 + c] + bias[c], 0.0f);
    g_fraw[(size_t)p * 32 + c] = v;
    if (c < 3) {
        float cv = pp[c];
        if (c == 0) g_px[p] = cv; else if (c == 1) g_py[p] = cv; else g_pz[p] = cv;
    }
}

// ---------------- prep: conv3 SoA + relu(cf @ W_c3 + b) ------------------------------
__global__ void prep_c3_kernel(const float* __restrict__ conv3,
                               const float* __restrict__ W,
                               const float* __restrict__ bias) {
    int gid = blockIdx.x * 256 + threadIdx.x;      // Bb*Mm*64 threads
    int p = gid >> 6, c = gid & 63;
    const float* fp = conv3 + (size_t)p * 67;
    float acc = 0.0f;
    #pragma unroll 8
    for (int k = 0; k < 64; k++) acc = fmaf(fp[3 + k], W[k * 64 + c], acc);
    acc = fmaxf(acc + bias[c], 0.0f);
    g_fc3[(size_t)p * 64 + c] = acc;
    if (c < 3) {
        float cv = fp[c];
        if (c == 0) g_qx[p] = cv; else if (c == 1) g_qy[p] = cv; else g_qz[p] = cv;
    }
}

// ---------------- ROI validity mask (bitwise-strict fp32, no contraction) ------------
__global__ void roi_mask_kernel(const float* __restrict__ points,
                                const float* __restrict__ bboxes) {
    int blk = blockIdx.x;                          // Bb*Nn/256 blocks, batch-aligned
    int b = blk / (Nn / 256);
    int t = threadIdx.x;
    __shared__ float rcx[Rr], rcy[Rr], rcz[Rr], rth[Rr];
    if (t < Rr) {
        const float* bb = bboxes + ((size_t)b * Rr + t) * 7;
        rcx[t] = bb[0]; rcy[t] = bb[1]; rcz[t] = bb[2];
        float hx = __fmul_rn(bb[3], 0.5f);
        float hy = __fmul_rn(bb[4], 0.5f);
        float hz = __fmul_rn(bb[5], 0.5f);
        float s = __fadd_rn(__fadd_rn(__fmul_rn(hx, hx), __fmul_rn(hy, hy)), __fmul_rn(hz, hz));
        rth[t] = __fadd_rn(__fsqrt_rn(s), 2.4f);
    }
    __syncthreads();
    int i = blk * 256 + t;
    const float* pp = points + (size_t)i * 5;
    float px = pp[0], py = pp[1], pz = pp[2];
    float best = 3.402823466e38f; int bi = 0;
    #pragma unroll 4
    for (int r = 0; r < Rr; r++) {
        float dx = __fsub_rn(px, rcx[r]);
        float dy = __fsub_rn(py, rcy[r]);
        float dz = __fsub_rn(pz, rcz[r]);
        float d2 = __fadd_rn(__fadd_rn(__fmul_rn(dx, dx), __fmul_rn(dy, dy)), __fmul_rn(dz, dz));
        if (d2 < best) { best = d2; bi = r; }     // strict < : first-index tie-break (argmin)
    }
    // min over sqrt == sqrt over min (monotone rounding)
    g_flag[i] = (__fsqrt_rn(best) < rth[bi]) ? 1 : 0;
}

// ---------------- order-preserving compaction of valid points ------------------------
__global__ void compact_kernel() {
    int b = blockIdx.x, t = threadIdx.x;           // 2 blocks x 1024
    __shared__ int warpTot[32];
    __shared__ int s_base;
    if (t == 0) s_base = 0;
    __syncthreads();
    for (int chunk = 0; chunk < Nn / 1024; chunk++) {
        int i = b * Nn + chunk * 1024 + t;
        int flag = g_flag[i];
        unsigned bal = __ballot_sync(0xffffffffu, flag);
        int lane = t & 31, w = t >> 5;
        if (lane == 0) warpTot[w] = __popc(bal);
        __syncthreads();
        int off = 0;
        for (int ww = 0; ww < w; ww++) off += warpTot[ww];
        if (flag) {
            int o = b * Nn + s_base + off + __popc(bal & ((1u << lane) - 1u));
            g_cx[o] = g_px[i]; g_cy[o] = g_py[i]; g_cz[o] = g_pz[i];
        }
        __syncthreads();
        if (t == 0) {
            int tot = 0;
            for (int ww = 0; ww < 32; ww++) tot += warpTot[ww];
            s_base += tot;
        }
        __syncthreads();
    }
    if (t == 0) g_vcount[b] = s_base;
}

// ---------------- FPS over compacted valid points (the serial bottleneck) ------------
__global__ void fps_kernel(float* __restrict__ out) {
    int b = blockIdx.x;
    int t = threadIdx.x;                           // 1024 threads
    extern __shared__ float sm[];
    float2* sxy = reinterpret_cast<float2*>(sm);   // [Nn] float2
    float*  szz = sm + 2 * Nn;                     // [Nn] float
    __shared__ float red_v[32];
    __shared__ int   red_i[32];
    __shared__ float s_b[3];
    int V = g_vcount[b];
    for (int i = t; i < V; i += 1024) {
        sxy[i] = make_float2(g_cx[b * Nn + i], g_cy[b * Nn + i]);
        szz[i] = g_cz[b * Nn + i];
    }
    float d[16];
    #pragma unroll
    for (int j = 0; j < 16; j++) d[j] = (t + j * 1024 < V) ? 1e10f : -3.0e38f;
    __syncthreads();

    float* outkp = out + (size_t)Bb * Kk * 128;    // keypoints section of d_out
    float bx = 0.f, by = 0.f, bz = 0.f;

    for (int k = 0; k < Kk; k++) {
        if (k > 0) { bx = s_b[0]; by = s_b[1]; bz = s_b[2]; }
        float bestv = -3.4e38f; int besti = 0x7fffffff;
        #pragma unroll
        for (int j = 0; j < 16; j++) {
            int ci = t + j * 1024;
            if (ci >= V) break;
            if (k > 0) {
                float2 xy = sxy[ci]; float zz = szz[ci];
                // strict IEEE per-op fp32, matching XLA HLO semantics (no FMA contraction)
                float dx = __fsub_rn(xy.x, bx);
                float dy = __fsub_rn(xy.y, by);
                float dz = __fsub_rn(zz, bz);
                float nd = __fadd_rn(__fadd_rn(__fmul_rn(dx, dx), __fmul_rn(dy, dy)),
                                     __fmul_rn(dz, dz));
                d[j] = fminf(d[j], nd);
            }
            if (d[j] > bestv) { bestv = d[j]; besti = ci; }   // ascending ci: first-max
        }
        // warp argmax reduce (larger value wins; tie -> smaller index)
        #pragma unroll
        for (int off = 16; off > 0; off >>= 1) {
            float ov = __shfl_down_sync(0xffffffffu, bestv, off);
            int   oi = __shfl_down_sync(0xffffffffu, besti, off);
            if (ov > bestv || (ov == bestv && oi < besti)) { bestv = ov; besti = oi; }
        }
        if ((t & 31) == 0) { red_v[t >> 5] = bestv; red_i[t >> 5] = besti; }
        __syncthreads();
        if (t < 32) {
            bestv = red_v[t]; besti = red_i[t];
            #pragma unroll
            for (int off = 16; off > 0; off >>= 1) {
                float ov = __shfl_down_sync(0xffffffffu, bestv, off);
                int   oi = __shfl_down_sync(0xffffffffu, besti, off);
                if (ov > bestv || (ov == bestv && oi < besti)) { bestv = ov; besti = oi; }
            }
            if (t == 0) {
                float2 xy = sxy[besti]; float zz = szz[besti];
                s_b[0] = xy.x; s_b[1] = xy.y; s_b[2] = zz;
                int row = b * Kk + k;
                g_kpx[row] = xy.x; g_kpy[row] = xy.y; g_kpz[row] = zz;
                outkp[(size_t)row * 3 + 0] = xy.x;
                outkp[(size_t)row * 3 + 1] = xy.y;
                outkp[(size_t)row * 3 + 2] = zz;
            }
        }
        __syncthreads();
    }
}

// ---------------- BEV bilinear gather ------------------------------------------------
__global__ void bev_kernel(const float* __restrict__ spatial) {
    int kpi = blockIdx.x, b = blockIdx.y, c = threadIdx.x;   // 256 threads = channels
    int row = b * Kk + kpi;
    float kx = g_kpx[row], ky = g_kpy[row];
    float x = ((kx - (-75.2f)) / 0.1f) / 8.0f;
    float y = ((ky - (-75.2f)) / 0.1f) / 8.0f;
    int x0 = (int)floorf(x); x0 = min(max(x0, 0), 187); int x1 = min(x0 + 1, 187);
    int y0 = (int)floorf(y); y0 = min(max(y0, 0), 187); int y1 = min(y0 + 1, 187);
    float xf0 = (float)x0, xf1 = (float)x1, yf0 = (float)y0, yf1 = (float)y1;
    float wa = (xf1 - x) * (yf1 - y);
    float wb2 = (xf1 - x) * (y - yf0);
    float wc2 = (x - xf0) * (yf1 - y);
    float wd = (x - xf0) * (y - yf0);
    const float* im = spatial + ((size_t)b * 256 + c) * 35344;
    float v = im[y0 * 188 + x0] * wa + im[y1 * 188 + x0] * wb2
            + im[y0 * 188 + x1] * wc2 + im[y1 * 188 + x1] * wd;
    g_feats[(size_t)row * 352 + c] = v;
}

// ---------------- raw-point radius aggregation (r=0.8, 32 feats) ---------------------
__global__ void raw_agg_kernel() {
    int blk = blockIdx.x;                          // Bb * (Kk/8) = 512 blocks
    int b = blk / (Kk / 8);
    int g = blk % (Kk / 8);
    int t = threadIdx.x;                           // 256
    __shared__ float kx[8], ky[8], kz[8];
    __shared__ float acc[8][33];                   // 32 feats + count
    if (t < 8) {
        int row = b * Kk + g * 8 + t;
        kx[t] = g_kpx[row]; ky[t] = g_kpy[row]; kz[t] = g_kpz[row];
    }
    for (int idx = t; idx < 8 * 33; idx += 256) ((float*)acc)[idx] = 0.0f;
    __syncthreads();
    for (int i = t; i < Nn; i += 256) {
        float px = g_px[b * Nn + i], py = g_py[b * Nn + i], pz = g_pz[b * Nn + i];
        const float* f = g_fraw + (size_t)(b * Nn + i) * 32;
        #pragma unroll
        for (int q = 0; q < 8; q++) {
            float dx = px - kx[q], dy = py - ky[q], dz = pz - kz[q];
            float d2 = fmaf(dx, dx, fmaf(dy, dy, dz * dz));
            if (d2 < 0.64f) {                      // f32(0.8*0.8 in f64) == 0.64f
                #pragma unroll
                for (int c = 0; c < 32; c++) atomicAdd(&acc[q][c], f[c]);
                atomicAdd(&acc[q][32], 1.0f);
            }
        }
    }
    __syncthreads();
    int q = t >> 5, c = t & 31;                    // 8*32 = 256 writers
    float cnt = fmaxf(acc[q][32], 1.0f);
    g_feats[(size_t)(b * Kk + g * 8 + q) * 352 + 256 + c] = acc[q][c] / cnt;
}

// ---------------- conv3 radius aggregation (r=1.6, 64 feats) -------------------------
__global__ void c3_agg_kernel() {
    int blk = blockIdx.x;                          // 512 blocks
    int b = blk / (Kk / 8);
    int g = blk % (Kk / 8);
    int t = threadIdx.x;                           // 256
    __shared__ float kx[8], ky[8], kz[8];
    __shared__ float acc[8][65];                   // 64 feats + count
    if (t < 8) {
        int row = b * Kk + g * 8 + t;
        kx[t] = g_kpx[row]; ky[t] = g_kpy[row]; kz[t] = g_kpz[row];
    }
    for (int idx = t; idx < 8 * 65; idx += 256) ((float*)acc)[idx] = 0.0f;
    __syncthreads();
    for (int i = t; i < Mm; i += 256) {
        float px = g_qx[b * Mm + i], py = g_qy[b * Mm + i], pz = g_qz[b * Mm + i];
        const float* f = g_fc3 + (size_t)(b * Mm + i) * 64;
        #pragma unroll
        for (int q = 0; q < 8; q++) {
            float dx = px - kx[q], dy = py - ky[q], dz = pz - kz[q];
            float d2 = fmaf(dx, dx, fmaf(dy, dy, dz * dz));
            if (d2 < 2.56f) {                      // f32(1.6*1.6 in f64) == 2.56f
                #pragma unroll
                for (int c = 0; c < 64; c++) atomicAdd(&acc[q][c], f[c]);
                atomicAdd(&acc[q][64], 1.0f);
            }
        }
    }
    __syncthreads();
    for (int idx = t; idx < 8 * 64; idx += 256) {
        int q = idx >> 6, c = idx & 63;
        float cnt = fmaxf(acc[q][64], 1.0f);
        g_feats[(size_t)(b * Kk + g * 8 + q) * 352 + 288 + c] = acc[q][c] / cnt;
    }
}

// ---------------- fuse GEMM (4096x352 @ 352x128) + BN + ReLU -------------------------
__global__ void fuse_kernel(const float* __restrict__ Wf,
                            const float* __restrict__ bn_g, const float* __restrict__ bn_b,
                            const float* __restrict__ bn_m, const float* __restrict__ bn_v,
                            float* __restrict__ out) {
    int blk = blockIdx.x;                          // 256 blocks x 16 rows
    int t = threadIdx.x;                           // 128 = output channels
    __shared__ float sf[16 * 352];
    int row0 = blk * 16;
    for (int idx = t; idx < 16 * 352; idx += 128)
        sf[idx] = g_feats[(size_t)row0 * 352 + idx];
    __syncthreads();
    float acc[16];
    #pragma unroll
    for (int r = 0; r < 16; r++) acc[r] = 0.0f;
    for (int k = 0; k < 352; k++) {
        float w = Wf[k * 128 + t];
        #pragma unroll
        for (int r = 0; r < 16; r++) acc[r] = fmaf(sf[r * 352 + k], w, acc[r]);
    }
    float sc = rsqrtf(bn_v[t] + 1e-5f) * bn_g[t];
    float mu = bn_m[t], be = bn_b[t];
    #pragma unroll
    for (int r = 0; r < 16; r++) {
        float v = (acc[r] - mu) * sc + be;
        out[(size_t)(row0 + r) * 128 + t] = fmaxf(v, 0.0f);
    }
}

// ---------------- launch -------------------------------------------------------------
extern "C" void kernel_launch(void* const* d_in, const int* in_sizes, int n_in,
                              void* d_out, int out_size) {
    const float* points  = (const float*)d_in[0];
    const float* bboxes  = (const float*)d_in[1];
    const float* spatial = (const float*)d_in[2];
    const float* conv3   = (const float*)d_in[3];
    const float* W_raw   = (const float*)d_in[4];
    const float* b_raw   = (const float*)d_in[5];
    const float* W_c3    = (const float*)d_in[6];
    const float* b_c3    = (const float*)d_in[7];
    const float* W_fuse  = (const float*)d_in[8];
    const float* bn_g    = (const float*)d_in[9];
    const float* bn_b    = (const float*)d_in[10];
    const float* bn_m    = (const float*)d_in[11];
    const float* bn_v    = (const float*)d_in[12];
    float* out = (float*)d_out;

    prep_raw_kernel<<<(Bb * Nn * 32) / 256, 256>>>(points, W_raw, b_raw);
    prep_c3_kernel<<<(Bb * Mm * 64) / 256, 256>>>(conv3, W_c3, b_c3);
    roi_mask_kernel<<<(Bb * Nn) / 256, 256>>>(points, bboxes);
    compact_kernel<<<Bb, 1024>>>();

    static const size_t fps_smem = (size_t)3 * Nn * sizeof(float);   // 196608 B
    cudaFuncSetAttribute(fps_kernel, cudaFuncAttributeMaxDynamicSharedMemorySize,
                         (int)fps_smem);
    fps_kernel<<<Bb, 1024, fps_smem>>>(out);

    bev_kernel<<<dim3(Kk, Bb), 256>>>(spatial);
    raw_agg_kernel<<<Bb * (Kk / 8), 256>>>();
    c3_agg_kernel<<<Bb * (Kk / 8), 256>>>();
    fuse_kernel<<<(Bb * Kk) / 16, 128>>>(W_fuse, bn_g, bn_b, bn_m, bn_v, out);
}

// round 3
// speedup vs baseline: 1.3577x; 1.3577x over previous
#include <cuda_runtime.h>

#define Bb 2
#define Nn 16384
#define Mm 8192
#define Kk 2048
#define Rr 128

// ---------------- scratch (__device__ globals; no allocation allowed) ----------------
__device__ float g_px[Bb*Nn], g_py[Bb*Nn], g_pz[Bb*Nn];
__device__ float g_qx[Bb*Mm], g_qy[Bb*Mm], g_qz[Bb*Mm];
__device__ float g_fraw[Bb*Nn*32];
__device__ float g_fc3[Bb*Mm*64];
__device__ int   g_flag[Bb*Nn];
__device__ float g_cx[Bb*Nn], g_cy[Bb*Nn], g_cz[Bb*Nn];
__device__ int   g_vcount[Bb];
__device__ float g_kpx[Bb*Kk], g_kpy[Bb*Kk], g_kpz[Bb*Kk];
__device__ float g_feats[Bb*Kk*352];

// ---------------- prep: point SoA + raw point features relu(pf @ W_raw + b) ----------
__global__ void prep_raw_kernel(const float* __restrict__ points,
                                const float* __restrict__ W,
                                const float* __restrict__ bias) {
    int gid = blockIdx.x * 256 + threadIdx.x;      // Bb*Nn*32 threads
    int p = gid >> 5, c = gid & 31;
    const float* pp = points + (size_t)p * 5;
    float v = fmaxf(pp[3] * W[c] + pp[4] * W[32 + c] + bias[c], 0.0f);
    g_fraw[(size_t)p * 32 + c] = v;
    if (c < 3) {
        float cv = pp[c];
        if (c == 0) g_px[p] = cv; else if (c == 1) g_py[p] = cv; else g_pz[p] = cv;
    }
}

// ---------------- prep: conv3 SoA + relu(cf @ W_c3 + b) ------------------------------
__global__ void prep_c3_kernel(const float* __restrict__ conv3,
                               const float* __restrict__ W,
                               const float* __restrict__ bias) {
    int gid = blockIdx.x * 256 + threadIdx.x;      // Bb*Mm*64 threads
    int p = gid >> 6, c = gid & 63;
    const float* fp = conv3 + (size_t)p * 67;
    float acc = 0.0f;
    #pragma unroll 8
    for (int k = 0; k < 64; k++) acc = fmaf(fp[3 + k], W[k * 64 + c], acc);
    acc = fmaxf(acc + bias[c], 0.0f);
    g_fc3[(size_t)p * 64 + c] = acc;
    if (c < 3) {
        float cv = fp[c];
        if (c == 0) g_qx[p] = cv; else if (c == 1) g_qy[p] = cv; else g_qz[p] = cv;
    }
}

// ---------------- ROI validity mask (bitwise-strict fp32, no contraction) ------------
__global__ void roi_mask_kernel(const float* __restrict__ points,
                                const float* __restrict__ bboxes) {
    int blk = blockIdx.x;                          // Bb*Nn/256 blocks, batch-aligned
    int b = blk / (Nn / 256);
    int t = threadIdx.x;
    __shared__ float rcx[Rr], rcy[Rr], rcz[Rr], rth[Rr];
    if (t < Rr) {
        const float* bb = bboxes + ((size_t)b * Rr + t) * 7;
        rcx[t] = bb[0]; rcy[t] = bb[1]; rcz[t] = bb[2];
        float hx = __fmul_rn(bb[3], 0.5f);
        float hy = __fmul_rn(bb[4], 0.5f);
        float hz = __fmul_rn(bb[5], 0.5f);
        float s = __fadd_rn(__fadd_rn(__fmul_rn(hx, hx), __fmul_rn(hy, hy)), __fmul_rn(hz, hz));
        rth[t] = __fadd_rn(__fsqrt_rn(s), 2.4f);
    }
    __syncthreads();
    int i = blk * 256 + t;
    const float* pp = points + (size_t)i * 5;
    float px = pp[0], py = pp[1], pz = pp[2];
    float best = 3.402823466e38f; int bi = 0;
    #pragma unroll 4
    for (int r = 0; r < Rr; r++) {
        float dx = __fsub_rn(px, rcx[r]);
        float dy = __fsub_rn(py, rcy[r]);
        float dz = __fsub_rn(pz, rcz[r]);
        float d2 = __fadd_rn(__fadd_rn(__fmul_rn(dx, dx), __fmul_rn(dy, dy)), __fmul_rn(dz, dz));
        if (d2 < best) { best = d2; bi = r; }     // strict < : first-index tie-break (argmin)
    }
    // min over sqrt == sqrt over min (monotone rounding)
    g_flag[i] = (__fsqrt_rn(best) < rth[bi]) ? 1 : 0;
}

// ---------------- order-preserving compaction: single block-scan pass ----------------
__global__ void compact_kernel() {
    int b = blockIdx.x, t = threadIdx.x;           // 2 blocks x 1024
    const int PT = Nn / 1024;                      // 16 consecutive elements/thread
    int lane = t & 31, w = t >> 5;
    int base = b * Nn + t * PT;
    unsigned fl = 0; int c = 0;
    #pragma unroll
    for (int i = 0; i < PT; i++) {
        int fi = g_flag[base + i];
        fl |= (unsigned)fi << i;
        c += fi;
    }
    // warp inclusive scan of per-thread counts
    int inc = c;
    #pragma unroll
    for (int off = 1; off < 32; off <<= 1) {
        int v = __shfl_up_sync(0xffffffffu, inc, off);
        if (lane >= off) inc += v;
    }
    __shared__ int wsum[32], wpre[32], s_total;
    if (lane == 31) wsum[w] = inc;
    __syncthreads();
    if (t < 32) {
        int v = wsum[t], iv = v;
        #pragma unroll
        for (int off = 1; off < 32; off <<= 1) {
            int u = __shfl_up_sync(0xffffffffu, iv, off);
            if (t >= off) iv += u;
        }
        wpre[t] = iv - v;                          // exclusive across warps
        if (t == 31) s_total = iv;
    }
    __syncthreads();
    int pos = b * Nn + wpre[w] + (inc - c);        // global exclusive prefix
    #pragma unroll
    for (int i = 0; i < PT; i++) {
        if ((fl >> i) & 1u) {
            int src = base + i;
            g_cx[pos] = g_px[src]; g_cy[pos] = g_py[src]; g_cz[pos] = g_pz[src];
            pos++;
        }
    }
    if (t == 0) {
        int tot = s_total;
        if (tot == 0) {                            // degenerate: mimic argmax-of-all-equal -> idx 0
            g_cx[b * Nn] = g_px[b * Nn];
            g_cy[b * Nn] = g_py[b * Nn];
            g_cz[b * Nn] = g_pz[b * Nn];
            tot = 1;
        }
        g_vcount[b] = tot;
    }
}

// ---------------- FPS: REDUX argmax, single barrier per iteration --------------------
__global__ void fps_kernel(float* __restrict__ out) {
    int b = blockIdx.x;
    int t = threadIdx.x;                           // 1024 threads
    extern __shared__ float sm[];
    float2* sxy = reinterpret_cast<float2*>(sm);   // [Nn] float2
    float*  szz = sm + 2 * Nn;                     // [Nn] float
    __shared__ unsigned red_v[2][32], red_i[2][32];
    int V = g_vcount[b];
    for (int i = t; i < V; i += 1024) {
        sxy[i] = make_float2(g_cx[b * Nn + i], g_cy[b * Nn + i]);
        szz[i] = g_cz[b * Nn + i];
    }
    float d[16];
    #pragma unroll
    for (int j = 0; j < 16; j++) d[j] = 1e10f;
    __syncthreads();

    float* outkp = out + (size_t)Bb * Kk * 128;    // keypoints section of d_out
    int lane = t & 31, widx = t >> 5;
    float bx = 0.f, by = 0.f, bz = 0.f;

    for (int k = 0; k < Kk; k++) {
        // update min-distance (strict per-op fp32 == XLA semantics) + local argmax
        float bestv = -1.0f; unsigned besti = 0xffffffffu;
        int have = 0;
        #pragma unroll
        for (int j = 0; j < 16; j++) {
            int ci = t + j * 1024;
            if (ci >= V) break;
            have = 1;
            if (k > 0) {
                float2 xy = sxy[ci]; float zz = szz[ci];
                float dx = __fsub_rn(xy.x, bx);
                float dy = __fsub_rn(xy.y, by);
                float dz = __fsub_rn(zz, bz);
                float nd = __fadd_rn(__fadd_rn(__fmul_rn(dx, dx), __fmul_rn(dy, dy)),
                                     __fmul_rn(dz, dz));
                d[j] = fminf(d[j], nd);
            }
            if (d[j] > bestv) { bestv = d[j]; besti = (unsigned)ci; }  // first-max (ci ascending)
        }
        // warp argmax via REDUX: d >= 0 so f32 bits are monotone as u32
        unsigned vb = have ? __float_as_uint(bestv) : 0u;
        unsigned m  = __reduce_max_sync(0xffffffffu, vb);
        unsigned cand = (vb == m) ? besti : 0xffffffffu;
        unsigned wbi  = __reduce_min_sync(0xffffffffu, cand);          // min index = first max
        int par = k & 1;                                               // double buffer (WAR safety)
        if (lane == 0) { red_v[par][widx] = m; red_i[par][widx] = wbi; }
        __syncthreads();
        // level-2: every warp reduces the 32 per-warp results redundantly (no 2nd barrier)
        unsigned v2 = red_v[par][lane];
        unsigned i2 = red_i[par][lane];
        unsigned gm = __reduce_max_sync(0xffffffffu, v2);
        unsigned c2 = (v2 == gm) ? i2 : 0xffffffffu;
        unsigned gbi = __reduce_min_sync(0xffffffffu, c2);
        // broadcast fetch of winning point straight from the smem point arrays
        float2 xy = sxy[gbi];
        bx = xy.x; by = xy.y; bz = szz[gbi];
        if (t == 0) {
            int row = b * Kk + k;
            g_kpx[row] = bx; g_kpy[row] = by; g_kpz[row] = bz;
            outkp[(size_t)row * 3 + 0] = bx;
            outkp[(size_t)row * 3 + 1] = by;
            outkp[(size_t)row * 3 + 2] = bz;
        }
    }
}

// ---------------- BEV bilinear gather ------------------------------------------------
__global__ void bev_kernel(const float* __restrict__ spatial) {
    int kpi = blockIdx.x, b = blockIdx.y, c = threadIdx.x;   // 256 threads = channels
    int row = b * Kk + kpi;
    float kx = g_kpx[row], ky = g_kpy[row];
    float x = ((kx - (-75.2f)) / 0.1f) / 8.0f;
    float y = ((ky - (-75.2f)) / 0.1f) / 8.0f;
    int x0 = (int)floorf(x); x0 = min(max(x0, 0), 187); int x1 = min(x0 + 1, 187);
    int y0 = (int)floorf(y); y0 = min(max(y0, 0), 187); int y1 = min(y0 + 1, 187);
    float xf0 = (float)x0, xf1 = (float)x1, yf0 = (float)y0, yf1 = (float)y1;
    float wa = (xf1 - x) * (yf1 - y);
    float wb2 = (xf1 - x) * (y - yf0);
    float wc2 = (x - xf0) * (yf1 - y);
    float wd = (x - xf0) * (y - yf0);
    const float* im = spatial + ((size_t)b * 256 + c) * 35344;
    float v = im[y0 * 188 + x0] * wa + im[y1 * 188 + x0] * wb2
            + im[y0 * 188 + x1] * wc2 + im[y1 * 188 + x1] * wd;
    g_feats[(size_t)row * 352 + c] = v;
}

// ---------------- raw-point radius aggregation (r=0.8, 32 feats) ---------------------
__global__ void raw_agg_kernel() {
    int blk = blockIdx.x;                          // Bb * (Kk/8) = 512 blocks
    int b = blk / (Kk / 8);
    int g = blk % (Kk / 8);
    int t = threadIdx.x;                           // 256
    __shared__ float kx[8], ky[8], kz[8];
    __shared__ float acc[8][33];                   // 32 feats + count
    if (t < 8) {
        int row = b * Kk + g * 8 + t;
        kx[t] = g_kpx[row]; ky[t] = g_kpy[row]; kz[t] = g_kpz[row];
    }
    for (int idx = t; idx < 8 * 33; idx += 256) ((float*)acc)[idx] = 0.0f;
    __syncthreads();
    for (int i = t; i < Nn; i += 256) {
        float px = g_px[b * Nn + i], py = g_py[b * Nn + i], pz = g_pz[b * Nn + i];
        const float* f = g_fraw + (size_t)(b * Nn + i) * 32;
        #pragma unroll
        for (int q = 0; q < 8; q++) {
            float dx = px - kx[q], dy = py - ky[q], dz = pz - kz[q];
            float d2 = fmaf(dx, dx, fmaf(dy, dy, dz * dz));
            if (d2 < 0.64f) {                      // f32(0.8*0.8 in f64) == 0.64f
                #pragma unroll
                for (int c = 0; c < 32; c++) atomicAdd(&acc[q][c], f[c]);
                atomicAdd(&acc[q][32], 1.0f);
            }
        }
    }
    __syncthreads();
    int q = t >> 5, c = t & 31;                    // 8*32 = 256 writers
    float cnt = fmaxf(acc[q][32], 1.0f);
    g_feats[(size_t)(b * Kk + g * 8 + q) * 352 + 256 + c] = acc[q][c] / cnt;
}

// ---------------- conv3 radius aggregation (r=1.6, 64 feats) -------------------------
__global__ void c3_agg_kernel() {
    int blk = blockIdx.x;                          // 512 blocks
    int b = blk / (Kk / 8);
    int g = blk % (Kk / 8);
    int t = threadIdx.x;                           // 256
    __shared__ float kx[8], ky[8], kz[8];
    __shared__ float acc[8][65];                   // 64 feats + count
    if (t < 8) {
        int row = b * Kk + g * 8 + t;
        kx[t] = g_kpx[row]; ky[t] = g_kpy[row]; kz[t] = g_kpz[row];
    }
    for (int idx = t; idx < 8 * 65; idx += 256) ((float*)acc)[idx] = 0.0f;
    __syncthreads();
    for (int i = t; i < Mm; i += 256) {
        float px = g_qx[b * Mm + i], py = g_qy[b * Mm + i], pz = g_qz[b * Mm + i];
        const float* f = g_fc3 + (size_t)(b * Mm + i) * 64;
        #pragma unroll
        for (int q = 0; q < 8; q++) {
            float dx = px - kx[q], dy = py - ky[q], dz = pz - kz[q];
            float d2 = fmaf(dx, dx, fmaf(dy, dy, dz * dz));
            if (d2 < 2.56f) {                      // f32(1.6*1.6 in f64) == 2.56f
                #pragma unroll
                for (int c = 0; c < 64; c++) atomicAdd(&acc[q][c], f[c]);
                atomicAdd(&acc[q][64], 1.0f);
            }
        }
    }
    __syncthreads();
    for (int idx = t; idx < 8 * 64; idx += 256) {
        int q = idx >> 6, c = idx & 63;
        float cnt = fmaxf(acc[q][64], 1.0f);
        g_feats[(size_t)(b * Kk + g * 8 + q) * 352 + 288 + c] = acc[q][c] / cnt;
    }
}

// ---------------- fuse GEMM (4096x352 @ 352x128) + BN + ReLU -------------------------
__global__ void fuse_kernel(const float* __restrict__ Wf,
                            const float* __restrict__ bn_g, const float* __restrict__ bn_b,
                            const float* __restrict__ bn_m, const float* __restrict__ bn_v,
                            float* __restrict__ out) {
    int blk = blockIdx.x;                          // 256 blocks x 16 rows
    int t = threadIdx.x;                           // 128 = output channels
    __shared__ float sf[16 * 352];
    int row0 = blk * 16;
    for (int idx = t; idx < 16 * 352; idx += 128)
        sf[idx] = g_feats[(size_t)row0 * 352 + idx];
    __syncthreads();
    float acc[16];
    #pragma unroll
    for (int r = 0; r < 16; r++) acc[r] = 0.0f;
    for (int k = 0; k < 352; k++) {
        float w = Wf[k * 128 + t];
        #pragma unroll
        for (int r = 0; r < 16; r++) acc[r] = fmaf(sf[r * 352 + k], w, acc[r]);
    }
    float sc = rsqrtf(bn_v[t] + 1e-5f) * bn_g[t];
    float mu = bn_m[t], be = bn_b[t];
    #pragma unroll
    for (int r = 0; r < 16; r++) {
        float v = (acc[r] - mu) * sc + be;
        out[(size_t)(row0 + r) * 128 + t] = fmaxf(v, 0.0f);
    }
}

// ---------------- launch -------------------------------------------------------------
extern "C" void kernel_launch(void* const* d_in, const int* in_sizes, int n_in,
                              void* d_out, int out_size) {
    const float* points  = (const float*)d_in[0];
    const float* bboxes  = (const float*)d_in[1];
    const float* spatial = (const float*)d_in[2];
    const float* conv3   = (const float*)d_in[3];
    const float* W_raw   = (const float*)d_in[4];
    const float* b_raw   = (const float*)d_in[5];
    const float* W_c3    = (const float*)d_in[6];
    const float* b_c3    = (const float*)d_in[7];
    const float* W_fuse  = (const float*)d_in[8];
    const float* bn_g    = (const float*)d_in[9];
    const float* bn_b    = (const float*)d_in[10];
    const float* bn_m    = (const float*)d_in[11];
    const float* bn_v    = (const float*)d_in[12];
    float* out = (float*)d_out;

    prep_raw_kernel<<<(Bb * Nn * 32) / 256, 256>>>(points, W_raw, b_raw);
    prep_c3_kernel<<<(Bb * Mm * 64) / 256, 256>>>(conv3, W_c3, b_c3);
    roi_mask_kernel<<<(Bb * Nn) / 256, 256>>>(points, bboxes);
    compact_kernel<<<Bb, 1024>>>();

    static const size_t fps_smem = (size_t)3 * Nn * sizeof(float);   // 196608 B
    cudaFuncSetAttribute(fps_kernel, cudaFuncAttributeMaxDynamicSharedMemorySize,
                         (int)fps_smem);
    fps_kernel<<<Bb, 1024, fps_smem>>>(out);

    bev_kernel<<<dim3(Kk, Bb), 256>>>(spatial);
    raw_agg_kernel<<<Bb * (Kk / 8), 256>>>();
    c3_agg_kernel<<<Bb * (Kk / 8), 256>>>();
    fuse_kernel<<<(Bb * Kk) / 16, 128>>>(W_fuse, bn_g, bn_b, bn_m, bn_v, out);
}